// round 8
// baseline (speedup 1.0000x reference)
#include <cuda_runtime.h>
#include <math.h>

#define NN 16384
#define NG 256
#define KK 50
#define NB 5
#define MAXC 192     // max nodes per graph (mean 64, sd 8 -> astronomically safe); must be < 256
#define WARPS 8
#define SPLIT 4
#define BIGD 1e10f

__device__ __forceinline__ float ex2_approx(float x) {
    float r; asm("ex2.approx.f32 %0, %1;" : "=f"(r) : "f"(x)); return r;
}
__device__ __forceinline__ float sqrt_approx(float x) {
    float r; asm("sqrt.approx.f32 %0, %1;" : "=f"(r) : "f"(x)); return r;
}

// Output layout (float32, out_size = 8*N*K):
//   [0,      nK)  : edge_index row 0 (src)
//   [nK,    2nK)  : edge_index row 1 (dst)
//   [2nK,   3nK)  : dist
//   [3nK,   8nK)  : rdf [nK,5] row-major
__global__ __launch_bounds__(256) void knn_rdf_kernel(
    const float* __restrict__ pos,
    const int*   __restrict__ batch_w,   // raw words of batch (int32 or int64 layout)
    float*       __restrict__ out)
{
    __shared__ float px[MAXC], py[MAXC], pz[MAXC], sqv[MAXC];
    __shared__ __align__(16) unsigned keys[WARPS][MAXC];  // fallback (cnt>64) only
    __shared__ int slotJ[WARPS][KK];                      // fallback only
    __shared__ int sRange[2];

    const int g   = blockIdx.x;
    const int tid = threadIdx.x;

    if (tid < 2) {
        // dtype detection: int64 layout has high word 0 at odd word index NN-1
        const bool is64 = (batch_w[NN - 1] == 0);
        const int target = g + tid;            // lower_bound(batch, g) / (batch, g+1)
        int lo = 0, hi = NN;
        while (lo < hi) {
            int mid = (lo + hi) >> 1;
            int bv = is64 ? batch_w[2 * mid] : batch_w[mid];
            if (bv < target) lo = mid + 1; else hi = mid;
        }
        sRange[tid] = lo;
    }
    __syncthreads();
    const int start = sRange[0];
    const int end   = sRange[1];
    int cnt = end - start;
    if (cnt <= 0) return;
    if (cnt > MAXC) cnt = MAXC;   // safety clamp (never expected)
    const int cntR = (cnt + 3) & ~3;

    // stage this graph's positions + squared norms
    for (int j = tid; j < cnt; j += blockDim.x) {
        float x = pos[3 * (start + j) + 0];
        float y = pos[3 * (start + j) + 1];
        float z = pos[3 * (start + j) + 2];
        px[j] = x; py[j] = y; pz[j] = z;
        sqv[j] = x * x + y * y + z * z;
    }
    __syncthreads();

    const int warp = tid >> 5, lane = tid & 31;
    const unsigned nK = (unsigned)NN * KK;     // 819200, fits 32-bit
    const float EA = -0.11541560327111707f;    // -0.08 * log2(e)
    const float ET =  0.57707801635558534f;    //  0.40 * log2(e)
    const float C1 = 0.60653065971263342360f;
    const float C2 = 0.13533528323661270231f;
    const float C3 = 0.01110899653824230650f;
    const float C4 = 3.35462627902511838821e-4f;
    const float padDist = sqrtf(BIGD);

    const int v = min(cnt - 1, KK);            // valid (non-padding) slots per node

    // emit one output slot s for node i (local), neighbor j (local, ignored if s>=v)
    auto emit = [&](int i, int s, int j) {
        const int ig = start + i;
        const unsigned eb = (unsigned)ig * KK;
        float fsrc, dist, r0, r1, r2, r3, r4;
        if (s < v) {
            const float d2 = sqv[i] + sqv[j]
                - 2.0f * (px[i] * px[j] + py[i] * py[j] + pz[i] * pz[j]);
            fsrc = (float)(start + j);
            dist = sqrt_approx(fmaxf(d2, 1e-12f));
            float A = ex2_approx(EA * dist * dist);
            float t = ex2_approx(ET * dist);
            r0 = A;
            float p = A * t; r1 = p * C1;
            p *= t;          r2 = p * C2;
            p *= t;          r3 = p * C3;
            p *= t;          r4 = p * C4;
        } else {
            int m = s - v;   // padding: masked indices ascending {0..start-1} ∪ {ig} ∪ {end..}
            int pidx = (m < start) ? m : ((m == start) ? ig : end + (m - start - 1));
            fsrc = (float)pidx;
            dist = padDist;
            r0 = r1 = r2 = r3 = r4 = 0.0f;
        }
        out[eb + s]          = fsrc;
        out[nK + eb + s]     = (float)ig;
        out[2u * nK + eb + s] = dist;
        float* rp = out + 3u * nK + 5u * (eb + s);
        rp[0] = r0; rp[1] = r1; rp[2] = r2; rp[3] = r3; rp[4] = r4;
    };

    auto makekey = [&](int i, int j) -> unsigned {
        unsigned key = 0xFFFFFFFFu;
        if (j < cnt && j != i) {
            float d2 = sqv[i] + sqv[j]
                - 2.0f * (px[i] * px[j] + py[i] * py[j] + pz[i] * pz[j]);
            unsigned ub = __float_as_uint(d2);
            ub ^= ((unsigned)((int)ub >> 31)) | 0x80000000u;   // monotonic float->uint
            key = (ub & 0xFFFFFF00u) | (unsigned)j;
        }
        return key;
    };

    if (cnt <= 64) {
        // ---------- fast path: dual interleaved 64-key register bitonic sorts ----------
        const int ia = warp + WARPS * blockIdx.y;   // [0,32)
        if (ia >= cnt) return;
        const int ib = ia + 32;
        const bool has2 = (ib < cnt);
        const int ib_s = has2 ? ib : ia;            // safe index for key build

        unsigned a0 = makekey(ia, lane),  a1 = makekey(ia, lane + 32);
        unsigned b0 = makekey(ib_s, lane), b1 = makekey(ib_s, lane + 32);

        // one compare-exchange layer applied to all 4 chains (2 independent sorts)
        #define LAYER4(d, kmA0, kmA1)                                              \
        {                                                                          \
            unsigned oa0 = __shfl_xor_sync(0xFFFFFFFFu, a0, (d));                  \
            unsigned oa1 = __shfl_xor_sync(0xFFFFFFFFu, a1, (d));                  \
            unsigned ob0 = __shfl_xor_sync(0xFFFFFFFFu, b0, (d));                  \
            unsigned ob1 = __shfl_xor_sync(0xFFFFFFFFu, b1, (d));                  \
            a0 = (kmA0) ? min(a0, oa0) : max(a0, oa0);                             \
            a1 = (kmA1) ? min(a1, oa1) : max(a1, oa1);                             \
            b0 = (kmA0) ? min(b0, ob0) : max(b0, ob0);                             \
            b1 = (kmA1) ? min(b1, ob1) : max(b1, ob1);                             \
        }

        // stages s=2..16: same predicate for both halves
        #pragma unroll
        for (int s = 2; s <= 16; s <<= 1) {
            #pragma unroll
            for (int d = s >> 1; d >= 1; d >>= 1) {
                bool km = ((lane & d) == 0) == ((lane & s) == 0);
                LAYER4(d, km, km);
            }
        }
        // stage s=32: half 0 ascending, half 1 descending
        #pragma unroll
        for (int d = 16; d >= 1; d >>= 1) {
            bool pm = ((lane & d) == 0);
            LAYER4(d, pm, !pm);
        }
        // stage s=64: d=32 in-register, then d=16..1 ascending
        { unsigned t0 = min(a0, a1), t1 = max(a0, a1); a0 = t0; a1 = t1; }
        { unsigned t0 = min(b0, b1), t1 = max(b0, b1); b0 = t0; b1 = t1; }
        #pragma unroll
        for (int d = 16; d >= 1; d >>= 1) {
            bool pm = ((lane & d) == 0);
            LAYER4(d, pm, pm);
        }
        #undef LAYER4

        // ranks: a0/b0 hold ranks 0..31 (by lane), a1/b1 ranks 32..63
        emit(ia, lane, (int)(a0 & 0xFFu));
        if (lane < KK - 32) emit(ia, lane + 32, (int)(a1 & 0xFFu));
        if (has2) {
            emit(ib, lane, (int)(b0 & 0xFFu));
            if (lane < KK - 32) emit(ib, lane + 32, (int)(b1 & 0xFFu));
        }
    } else {
        // ---------- fallback: counting rank via smem keys (proven path) ----------
        unsigned* kw = keys[warp];
        for (int i = warp + WARPS * blockIdx.y; i < cnt; i += WARPS * SPLIT) {
            for (int j = lane; j < cntR; j += 32)
                kw[j] = makekey(i, j);
            __syncwarp();
            {
                const int j0 = lane, j1 = lane + 32;
                const unsigned k0 = kw[j0];
                const unsigned k1 = (j1 < cntR) ? kw[j1] : 0xFFFFFFFFu;
                int r0 = 0, r1 = 0;
                #pragma unroll 4
                for (int kb = 0; kb < cntR; kb += 4) {
                    const uint4 q = *(const uint4*)&kw[kb];
                    r0 += (q.x < k0) + (q.y < k0) + (q.z < k0) + (q.w < k0);
                    r1 += (q.x < k1) + (q.y < k1) + (q.z < k1) + (q.w < k1);
                }
                if (r0 < KK) slotJ[warp][r0] = j0;
                if (r1 < KK) slotJ[warp][r1] = j1;
            }
            for (int jb = 64; jb < cnt; jb += 32) {
                const int j0 = jb + lane;
                const unsigned k0 = (j0 < cntR) ? kw[j0] : 0xFFFFFFFFu;
                int r0 = 0;
                #pragma unroll 4
                for (int kb = 0; kb < cntR; kb += 4) {
                    const uint4 q = *(const uint4*)&kw[kb];
                    r0 += (q.x < k0) + (q.y < k0) + (q.z < k0) + (q.w < k0);
                }
                if (r0 < KK) slotJ[warp][r0] = j0;
            }
            __syncwarp();
            for (int s = lane; s < KK; s += 32)
                emit(i, s, (s < v) ? slotJ[warp][s] : 0);
            __syncwarp();
        }
    }
}

extern "C" void kernel_launch(void* const* d_in, const int* in_sizes, int n_in,
                              void* d_out, int out_size)
{
    const float* pos    = (const float*)d_in[0];
    const int*   batchw = (const int*)d_in[1];
    float*       out    = (float*)d_out;
    dim3 grid(NG, SPLIT);
    knn_rdf_kernel<<<grid, 256>>>(pos, batchw, out);
}

// round 9
// speedup vs baseline: 1.0889x; 1.0889x over previous
#include <cuda_runtime.h>
#include <math.h>

#define NN 16384
#define NG 256
#define KK 50
#define NB 5
#define MAXC 192     // max nodes per graph (mean 64, sd 8 -> astronomically safe); must be < 256
#define WARPS 8
#define SPLIT 8
#define BIGD 1e10f

__device__ __forceinline__ float ex2_approx(float x) {
    float r; asm("ex2.approx.f32 %0, %1;" : "=f"(r) : "f"(x)); return r;
}
__device__ __forceinline__ float sqrt_approx(float x) {
    float r; asm("sqrt.approx.f32 %0, %1;" : "=f"(r) : "f"(x)); return r;
}

// one bitonic compare-exchange layer step (cross-lane, distance d)
__device__ __forceinline__ unsigned cmpex(unsigned k, int d, bool keep_min) {
    unsigned o = __shfl_xor_sync(0xFFFFFFFFu, k, d);
    unsigned mn = min(k, o), mx = max(k, o);
    return keep_min ? mn : mx;
}

// Output layout (float32, out_size = 8*N*K):
//   [0,      nK)  : edge_index row 0 (src)
//   [nK,    2nK)  : edge_index row 1 (dst)
//   [2nK,   3nK)  : dist
//   [3nK,   8nK)  : rdf [nK,5] row-major
__global__ __launch_bounds__(256, 8) void knn_rdf_kernel(
    const float* __restrict__ pos,
    const int*   __restrict__ batch_w,   // raw words of batch (int32 or int64 layout)
    float*       __restrict__ out)
{
    __shared__ float px[MAXC], py[MAXC], pz[MAXC], sqv[MAXC];
    __shared__ __align__(16) unsigned keys[WARPS][MAXC];  // fallback (cnt>64) only
    __shared__ unsigned slotK[WARPS][KK];                 // fallback only
    __shared__ int sRange[2];

    const int g   = blockIdx.x;
    const int tid = threadIdx.x;

    if (tid < 2) {
        // dtype detection: int64 layout has high word 0 at odd word index NN-1
        const bool is64 = (batch_w[NN - 1] == 0);
        const int target = g + tid;            // lower_bound(batch, g) / (batch, g+1)
        int lo = 0, hi = NN;
        while (lo < hi) {
            int mid = (lo + hi) >> 1;
            int bv = is64 ? batch_w[2 * mid] : batch_w[mid];
            if (bv < target) lo = mid + 1; else hi = mid;
        }
        sRange[tid] = lo;
    }
    __syncthreads();
    const int start = sRange[0];
    const int end   = sRange[1];
    int cnt = end - start;
    if (cnt <= 0) return;
    if (cnt > MAXC) cnt = MAXC;   // safety clamp (never expected)
    const int cntR = (cnt + 3) & ~3;

    // stage this graph's positions + squared norms
    for (int j = tid; j < cnt; j += blockDim.x) {
        float x = pos[3 * (start + j) + 0];
        float y = pos[3 * (start + j) + 1];
        float z = pos[3 * (start + j) + 2];
        px[j] = x; py[j] = y; pz[j] = z;
        sqv[j] = x * x + y * y + z * z;
    }
    __syncthreads();

    const int warp = tid >> 5, lane = tid & 31;
    const unsigned nK = (unsigned)NN * KK;     // 819200, fits 32-bit
    const float EA = -0.11541560327111707f;    // -0.08 * log2(e)
    const float ET =  0.57707801635558534f;    //  0.40 * log2(e)
    const float C1 = 0.60653065971263342360f;
    const float C2 = 0.13533528323661270231f;
    const float C3 = 0.01110899653824230650f;
    const float C4 = 3.35462627902511838821e-4f;
    const float padDist = sqrtf(BIGD);

    const int v = min(cnt - 1, KK);            // valid (non-padding) slots per node

    // emit slot s of node i directly from a sort key (d2 decoded from key bits)
    auto emitk = [&](int i, int s, unsigned key) {
        const int ig = start + i;
        const unsigned eb = (unsigned)ig * KK;
        float fsrc, dist, r0, r1, r2, r3, r4;
        if (s < v) {
            const int j = (int)(key & 0xFFu);
            unsigned ub = (key & 0xFFFFFF00u) | 0x80u;      // midpoint-restore low bits
            unsigned bits = (ub & 0x80000000u) ? (ub ^ 0x80000000u) : ~ub;
            const float d2 = __uint_as_float(bits);
            fsrc = (float)(start + j);
            dist = sqrt_approx(fmaxf(d2, 1e-12f));
            float A = ex2_approx(EA * dist * dist);
            float t = ex2_approx(ET * dist);
            r0 = A;
            float p = A * t; r1 = p * C1;
            p *= t;          r2 = p * C2;
            p *= t;          r3 = p * C3;
            p *= t;          r4 = p * C4;
        } else {
            int m = s - v;   // padding: masked indices ascending {0..start-1} ∪ {ig} ∪ {end..}
            int pidx = (m < start) ? m : ((m == start) ? ig : end + (m - start - 1));
            fsrc = (float)pidx;
            dist = padDist;
            r0 = r1 = r2 = r3 = r4 = 0.0f;
        }
        out[eb + s]           = fsrc;
        out[nK + eb + s]      = (float)ig;
        out[2u * nK + eb + s] = dist;
        float* rp = out + 3u * nK + 5u * (eb + s);
        rp[0] = r0; rp[1] = r1; rp[2] = r2; rp[3] = r3; rp[4] = r4;
    };

    auto makekey = [&](int i, int j) -> unsigned {
        unsigned key = 0xFFFFFFFFu;
        if (j < cnt && j != i) {
            float d2 = sqv[i] + sqv[j]
                - 2.0f * (px[i] * px[j] + py[i] * py[j] + pz[i] * pz[j]);
            unsigned ub = __float_as_uint(d2);
            ub ^= ((unsigned)((int)ub >> 31)) | 0x80000000u;   // monotonic float->uint
            key = (ub & 0xFFFFFF00u) | (unsigned)j;
        }
        return key;
    };

    if (cnt <= 64) {
        // ---------- fast path: 64-key register bitonic sort, one node per warp ----------
        const int i = warp + WARPS * blockIdx.y;   // [0,64)
        if (i >= cnt) return;

        unsigned k0 = makekey(i, lane);
        unsigned k1 = makekey(i, lane + 32);

        // stages s=2..16: same keep_min predicate for both registers
        #pragma unroll
        for (int s = 2; s <= 16; s <<= 1) {
            #pragma unroll
            for (int d = s >> 1; d >= 1; d >>= 1) {
                bool km = ((lane & d) == 0) == ((lane & s) == 0);
                k0 = cmpex(k0, d, km);
                k1 = cmpex(k1, d, km);
            }
        }
        // stage s=32: r0 ascending, r1 descending
        #pragma unroll
        for (int d = 16; d >= 1; d >>= 1) {
            bool pm = ((lane & d) == 0);
            k0 = cmpex(k0, d, pm);
            k1 = cmpex(k1, d, !pm);
        }
        // stage s=64: d=32 in-register, then d=16..1 ascending
        { unsigned a = min(k0, k1), b = max(k0, k1); k0 = a; k1 = b; }
        #pragma unroll
        for (int d = 16; d >= 1; d >>= 1) {
            bool pm = ((lane & d) == 0);
            k0 = cmpex(k0, d, pm);
            k1 = cmpex(k1, d, pm);
        }

        // ranks 0..31 in k0 (by lane), ranks 32..63 in k1
        emitk(i, lane, k0);
        if (lane < KK - 32) emitk(i, lane + 32, k1);
    } else {
        // ---------- fallback: counting rank via smem keys (proven path) ----------
        unsigned* kw = keys[warp];
        for (int i = warp + WARPS * blockIdx.y; i < cnt; i += WARPS * SPLIT) {
            for (int j = lane; j < cntR; j += 32)
                kw[j] = makekey(i, j);
            __syncwarp();
            {
                const int j0 = lane, j1 = lane + 32;
                const unsigned k0 = kw[j0];
                const unsigned k1 = (j1 < cntR) ? kw[j1] : 0xFFFFFFFFu;
                int r0 = 0, r1 = 0;
                #pragma unroll 4
                for (int kb = 0; kb < cntR; kb += 4) {
                    const uint4 q = *(const uint4*)&kw[kb];
                    r0 += (q.x < k0) + (q.y < k0) + (q.z < k0) + (q.w < k0);
                    r1 += (q.x < k1) + (q.y < k1) + (q.z < k1) + (q.w < k1);
                }
                if (r0 < KK) slotK[warp][r0] = k0;
                if (r1 < KK) slotK[warp][r1] = k1;
            }
            for (int jb = 64; jb < cnt; jb += 32) {
                const int j0 = jb + lane;
                const unsigned k0 = (j0 < cntR) ? kw[j0] : 0xFFFFFFFFu;
                int r0 = 0;
                #pragma unroll 4
                for (int kb = 0; kb < cntR; kb += 4) {
                    const uint4 q = *(const uint4*)&kw[kb];
                    r0 += (q.x < k0) + (q.y < k0) + (q.z < k0) + (q.w < k0);
                }
                if (r0 < KK) slotK[warp][r0] = k0;
            }
            __syncwarp();
            for (int s = lane; s < KK; s += 32)
                emitk(i, s, (s < v) ? slotK[warp][s] : 0u);
            __syncwarp();
        }
    }
}

extern "C" void kernel_launch(void* const* d_in, const int* in_sizes, int n_in,
                              void* d_out, int out_size)
{
    const float* pos    = (const float*)d_in[0];
    const int*   batchw = (const int*)d_in[1];
    float*       out    = (float*)d_out;
    dim3 grid(NG, SPLIT);
    knn_rdf_kernel<<<grid, 256>>>(pos, batchw, out);
}

// round 10
// speedup vs baseline: 1.2212x; 1.1215x over previous
#include <cuda_runtime.h>
#include <math.h>

#define NN 16384
#define NG 256
#define KK 50
#define NB 5
#define MAXC 192     // hard cap; counting fallback handles (128, 192]
#define WARPS 8
#define SPLIT 8
#define BIGD 1e10f

__device__ __forceinline__ float ex2_approx(float x) {
    float r; asm("ex2.approx.f32 %0, %1;" : "=f"(r) : "f"(x)); return r;
}
__device__ __forceinline__ float sqrt_approx(float x) {
    float r; asm("sqrt.approx.f32 %0, %1;" : "=f"(r) : "f"(x)); return r;
}

// one bitonic compare-exchange step (cross-lane, distance d)
__device__ __forceinline__ unsigned cmpex(unsigned k, int d, bool keep_min) {
    unsigned o = __shfl_xor_sync(0xFFFFFFFFu, k, d);
    unsigned mn = min(k, o), mx = max(k, o);
    return keep_min ? mn : mx;
}

// Output layout (float32, out_size = 8*N*K):
//   [0,      nK)  : edge_index row 0 (src)
//   [nK,    2nK)  : edge_index row 1 (dst)
//   [2nK,   3nK)  : dist
//   [3nK,   8nK)  : rdf [nK,5] row-major
__global__ __launch_bounds__(256, 8) void knn_rdf_kernel(
    const float* __restrict__ pos,
    const int*   __restrict__ batch_w,   // raw words of batch (int32 or int64 layout)
    float*       __restrict__ out)
{
    __shared__ float px[MAXC], py[MAXC], pz[MAXC], sqv[MAXC];
    __shared__ __align__(16) unsigned keys[WARPS][MAXC];  // fallback (cnt>128) only
    __shared__ unsigned slotK[WARPS][KK];                 // fallback only
    __shared__ int sRange[2];

    const int g   = blockIdx.x;
    const int tid = threadIdx.x;

    if (tid < 2) {
        // dtype detection: int64 layout has high word 0 at odd word index NN-1
        const bool is64 = (batch_w[NN - 1] == 0);
        const int target = g + tid;            // lower_bound(batch, g) / (batch, g+1)
        int lo = 0, hi = NN;
        while (lo < hi) {
            int mid = (lo + hi) >> 1;
            int bv = is64 ? batch_w[2 * mid] : batch_w[mid];
            if (bv < target) lo = mid + 1; else hi = mid;
        }
        sRange[tid] = lo;
    }
    __syncthreads();
    const int start = sRange[0];
    const int end   = sRange[1];
    int cnt = end - start;
    if (cnt <= 0) return;
    if (cnt > MAXC) cnt = MAXC;   // safety clamp (never expected)
    const int cntR = (cnt + 3) & ~3;

    // stage this graph's positions + squared norms
    for (int j = tid; j < cnt; j += blockDim.x) {
        float x = pos[3 * (start + j) + 0];
        float y = pos[3 * (start + j) + 1];
        float z = pos[3 * (start + j) + 2];
        px[j] = x; py[j] = y; pz[j] = z;
        sqv[j] = x * x + y * y + z * z;
    }
    __syncthreads();

    const int warp = tid >> 5, lane = tid & 31;
    const unsigned nK = (unsigned)NN * KK;     // 819200, fits 32-bit
    const float EA = -0.11541560327111707f;    // -0.08 * log2(e)
    const float ET =  0.57707801635558534f;    //  0.40 * log2(e)
    const float C1 = 0.60653065971263342360f;
    const float C2 = 0.13533528323661270231f;
    const float C3 = 0.01110899653824230650f;
    const float C4 = 3.35462627902511838821e-4f;
    const float padDist = sqrtf(BIGD);

    const int v = min(cnt - 1, KK);            // valid (non-padding) slots per node

    // emit slot s of node i directly from a sort key (d2 decoded from key bits)
    auto emitk = [&](int i, int s, unsigned key) {
        const int ig = start + i;
        const unsigned eb = (unsigned)ig * KK;
        float fsrc, dist, r0, r1, r2, r3, r4;
        if (s < v) {
            const int j = (int)(key & 0xFFu);
            unsigned ub = (key & 0xFFFFFF00u) | 0x80u;      // midpoint-restore low bits
            unsigned bits = (ub & 0x80000000u) ? (ub ^ 0x80000000u) : ~ub;
            const float d2 = __uint_as_float(bits);
            fsrc = (float)(start + j);
            dist = sqrt_approx(fmaxf(d2, 1e-12f));
            float A = ex2_approx(EA * dist * dist);
            float t = ex2_approx(ET * dist);
            r0 = A;
            float p = A * t; r1 = p * C1;
            p *= t;          r2 = p * C2;
            p *= t;          r3 = p * C3;
            p *= t;          r4 = p * C4;
        } else {
            int m = s - v;   // padding: masked indices ascending {0..start-1} ∪ {ig} ∪ {end..}
            int pidx = (m < start) ? m : ((m == start) ? ig : end + (m - start - 1));
            fsrc = (float)pidx;
            dist = padDist;
            r0 = r1 = r2 = r3 = r4 = 0.0f;
        }
        out[eb + s]           = fsrc;
        out[nK + eb + s]      = (float)ig;
        out[2u * nK + eb + s] = dist;
        float* rp = out + 3u * nK + 5u * (eb + s);
        rp[0] = r0; rp[1] = r1; rp[2] = r2; rp[3] = r3; rp[4] = r4;
    };

    auto makekey = [&](int i, int j) -> unsigned {
        unsigned key = 0xFFFFFFFFu;
        if (j < cnt && j != i) {
            float d2 = sqv[i] + sqv[j]
                - 2.0f * (px[i] * px[j] + py[i] * py[j] + pz[i] * pz[j]);
            unsigned ub = __float_as_uint(d2);
            ub ^= ((unsigned)((int)ub >> 31)) | 0x80000000u;   // monotonic float->uint
            key = (ub & 0xFFFFFF00u) | (unsigned)j;
        }
        return key;
    };

    if (cnt <= 64) {
        // ---------- fast path A: 64-key register bitonic sort, one node per warp ----------
        const int i = warp + WARPS * blockIdx.y;   // [0,64)
        if (i >= cnt) return;

        unsigned k0 = makekey(i, lane);
        unsigned k1 = makekey(i, lane + 32);

        #pragma unroll
        for (int s = 2; s <= 16; s <<= 1) {
            #pragma unroll
            for (int d = s >> 1; d >= 1; d >>= 1) {
                bool km = ((lane & d) == 0) == ((lane & s) == 0);
                k0 = cmpex(k0, d, km);
                k1 = cmpex(k1, d, km);
            }
        }
        #pragma unroll
        for (int d = 16; d >= 1; d >>= 1) {       // stage s=32
            bool pm = ((lane & d) == 0);
            k0 = cmpex(k0, d, pm);
            k1 = cmpex(k1, d, !pm);
        }
        { unsigned a = min(k0, k1), b = max(k0, k1); k0 = a; k1 = b; }  // s=64, d=32
        #pragma unroll
        for (int d = 16; d >= 1; d >>= 1) {
            bool pm = ((lane & d) == 0);
            k0 = cmpex(k0, d, pm);
            k1 = cmpex(k1, d, pm);
        }

        emitk(i, lane, k0);
        if (lane < KK - 32) emitk(i, lane + 32, k1);
    } else if (cnt <= 128) {
        // ---------- fast path B: 128-key register bitonic sort (4 regs/lane) ----------
        // element e = lane + 32*r; after ascending sort, key at e has rank e.
        for (int i = warp + WARPS * blockIdx.y; i < cnt; i += 64) {
            unsigned k0 = makekey(i, lane);
            unsigned k1 = makekey(i, lane + 32);
            unsigned k2 = makekey(i, lane + 64);
            unsigned k3 = makekey(i, lane + 96);

            // stages s=2..16: cross-lane, same predicate all regs
            #pragma unroll
            for (int s = 2; s <= 16; s <<= 1) {
                #pragma unroll
                for (int d = s >> 1; d >= 1; d >>= 1) {
                    bool km = ((lane & d) == 0) == ((lane & s) == 0);
                    k0 = cmpex(k0, d, km);
                    k1 = cmpex(k1, d, km);
                    k2 = cmpex(k2, d, km);
                    k3 = cmpex(k3, d, km);
                }
            }
            // stage s=32: (e&32)==0 <=> r even
            #pragma unroll
            for (int d = 16; d >= 1; d >>= 1) {
                bool pm = ((lane & d) == 0);
                k0 = cmpex(k0, d, pm);
                k1 = cmpex(k1, d, !pm);
                k2 = cmpex(k2, d, pm);
                k3 = cmpex(k3, d, !pm);
            }
            // stage s=64: d=32 in-register; direction by (e&64): r<2 asc, r>=2 desc
            { unsigned a = min(k0, k1), b = max(k0, k1); k0 = a; k1 = b; }
            { unsigned a = max(k2, k3), b = min(k2, k3); k2 = a; k3 = b; }
            #pragma unroll
            for (int d = 16; d >= 1; d >>= 1) {
                bool pm = ((lane & d) == 0);
                k0 = cmpex(k0, d, pm);
                k1 = cmpex(k1, d, pm);
                k2 = cmpex(k2, d, !pm);
                k3 = cmpex(k3, d, !pm);
            }
            // stage s=128: d=64, d=32 in-register, then d=16..1 all ascending
            { unsigned a = min(k0, k2), b = max(k0, k2); k0 = a; k2 = b; }
            { unsigned a = min(k1, k3), b = max(k1, k3); k1 = a; k3 = b; }
            { unsigned a = min(k0, k1), b = max(k0, k1); k0 = a; k1 = b; }
            { unsigned a = min(k2, k3), b = max(k2, k3); k2 = a; k3 = b; }
            #pragma unroll
            for (int d = 16; d >= 1; d >>= 1) {
                bool pm = ((lane & d) == 0);
                k0 = cmpex(k0, d, pm);
                k1 = cmpex(k1, d, pm);
                k2 = cmpex(k2, d, pm);
                k3 = cmpex(k3, d, pm);
            }

            // ranks 0..31 in k0, 32..63 in k1 (k2,k3 = ranks >= 64, unused)
            emitk(i, lane, k0);
            if (lane < KK - 32) emitk(i, lane + 32, k1);
        }
    } else {
        // ---------- fallback (cnt>128, ~never): counting rank via smem keys ----------
        unsigned* kw = keys[warp];
        for (int i = warp + WARPS * blockIdx.y; i < cnt; i += WARPS * SPLIT) {
            for (int j = lane; j < cntR; j += 32)
                kw[j] = makekey(i, j);
            __syncwarp();
            {
                const int j0 = lane, j1 = lane + 32;
                const unsigned k0 = kw[j0];
                const unsigned k1 = (j1 < cntR) ? kw[j1] : 0xFFFFFFFFu;
                int r0 = 0, r1 = 0;
                #pragma unroll 4
                for (int kb = 0; kb < cntR; kb += 4) {
                    const uint4 q = *(const uint4*)&kw[kb];
                    r0 += (q.x < k0) + (q.y < k0) + (q.z < k0) + (q.w < k0);
                    r1 += (q.x < k1) + (q.y < k1) + (q.z < k1) + (q.w < k1);
                }
                if (r0 < KK) slotK[warp][r0] = k0;
                if (r1 < KK) slotK[warp][r1] = k1;
            }
            for (int jb = 64; jb < cnt; jb += 32) {
                const int j0 = jb + lane;
                const unsigned k0 = (j0 < cntR) ? kw[j0] : 0xFFFFFFFFu;
                int r0 = 0;
                #pragma unroll 4
                for (int kb = 0; kb < cntR; kb += 4) {
                    const uint4 q = *(const uint4*)&kw[kb];
                    r0 += (q.x < k0) + (q.y < k0) + (q.z < k0) + (q.w < k0);
                }
                if (r0 < KK) slotK[warp][r0] = k0;
            }
            __syncwarp();
            for (int s = lane; s < KK; s += 32)
                emitk(i, s, (s < v) ? slotK[warp][s] : 0u);
            __syncwarp();
        }
    }
}

extern "C" void kernel_launch(void* const* d_in, const int* in_sizes, int n_in,
                              void* d_out, int out_size)
{
    const float* pos    = (const float*)d_in[0];
    const int*   batchw = (const int*)d_in[1];
    float*       out    = (float*)d_out;
    dim3 grid(NG, SPLIT);
    knn_rdf_kernel<<<grid, 256>>>(pos, batchw, out);
}

// round 11
// speedup vs baseline: 1.3243x; 1.0845x over previous
#include <cuda_runtime.h>
#include <math.h>

#define NN 16384
#define NG 256
#define KK 50
#define NB 5
#define MAXC 192     // hard cap; counting fallback handles (128, 192]
#define WARPS 8
#define SPLIT 16
#define BIGD 1e10f

__device__ __forceinline__ float ex2_approx(float x) {
    float r; asm("ex2.approx.f32 %0, %1;" : "=f"(r) : "f"(x)); return r;
}
__device__ __forceinline__ float sqrt_approx(float x) {
    float r; asm("sqrt.approx.f32 %0, %1;" : "=f"(r) : "f"(x)); return r;
}

// one bitonic compare-exchange step (cross-lane, distance d)
__device__ __forceinline__ unsigned cmpex(unsigned k, int d, bool keep_min) {
    unsigned o = __shfl_xor_sync(0xFFFFFFFFu, k, d);
    unsigned mn = min(k, o), mx = max(k, o);
    return keep_min ? mn : mx;
}

// Output layout (float32, out_size = 8*N*K):
//   [0,      nK)  : edge_index row 0 (src)
//   [nK,    2nK)  : edge_index row 1 (dst)
//   [2nK,   3nK)  : dist
//   [3nK,   8nK)  : rdf [nK,5] row-major
__global__ __launch_bounds__(256, 8) void knn_rdf_kernel(
    const float* __restrict__ pos,
    const int*   __restrict__ batch_w,   // raw words of batch (int32 or int64 layout)
    float*       __restrict__ out)
{
    __shared__ float px[MAXC], py[MAXC], pz[MAXC], sqv[MAXC];
    __shared__ __align__(16) unsigned keys[WARPS][MAXC];  // fallback (cnt>128) only
    __shared__ unsigned slotK[WARPS][KK];                 // fallback only

    const int g   = blockIdx.x;
    const int tid = threadIdx.x;

    // ---- parallel 2-level lower_bound for g and g+1 (no dependent LDG chain) ----
    const bool is64 = (batch_w[NN - 1] == 0);   // int64 layout: high word at odd index
    auto bval = [&](int idx) -> int { return batch_w[is64 ? 2 * idx : idx]; };

    // level 1: coarse samples at stride 64 (one load per thread, parallel)
    const int vc = bval(min(tid * 64, NN - 1) & ~((tid * 64 >= NN) ? 0 : 0));  // tid*64 < NN for tid<256
    const int cc_a = __syncthreads_count(vc < g);
    const int cc_b = __syncthreads_count(vc < g + 1);
    // level 2: 64-wide windows (64*cc-63 .. 64*cc); idx<0 counts as "< target"
    int pa = 0, pb = 0;
    if (tid < 64) {
        int ia = 64 * cc_a - 63 + tid;
        int ib = 64 * cc_b - 63 + tid;
        pa = (ia < 0) || (ia < NN && bval(ia) < g);
        pb = (ib < 0) || (ib < NN && bval(ib) < g + 1);
    }
    const int start = (64 * cc_a - 63) + __syncthreads_count(pa);
    const int end   = (64 * cc_b - 63) + __syncthreads_count(pb);

    int cnt = end - start;
    if (cnt <= 0) return;
    if (cnt > MAXC) cnt = MAXC;   // safety clamp (never expected)
    // whole-block early exit: this block's warps own nodes [8*y, 8*y+8) (+ fallback strides)
    if (cnt <= 128 && WARPS * blockIdx.y >= cnt) return;
    const int cntR = (cnt + 3) & ~3;

    // stage this graph's positions + squared norms
    for (int j = tid; j < cnt; j += blockDim.x) {
        float x = pos[3 * (start + j) + 0];
        float y = pos[3 * (start + j) + 1];
        float z = pos[3 * (start + j) + 2];
        px[j] = x; py[j] = y; pz[j] = z;
        sqv[j] = x * x + y * y + z * z;
    }
    __syncthreads();

    const int warp = tid >> 5, lane = tid & 31;
    const unsigned nK = (unsigned)NN * KK;     // 819200, fits 32-bit
    const float EA = -0.11541560327111707f;    // -0.08 * log2(e)
    const float ET =  0.57707801635558534f;    //  0.40 * log2(e)
    const float C1 = 0.60653065971263342360f;
    const float C2 = 0.13533528323661270231f;
    const float C3 = 0.01110899653824230650f;
    const float C4 = 3.35462627902511838821e-4f;
    const float padDist = sqrtf(BIGD);

    const int v = min(cnt - 1, KK);            // valid (non-padding) slots per node

    // emit slot s of node i directly from a sort key (d2 decoded from key bits)
    auto emitk = [&](int i, int s, unsigned key) {
        const int ig = start + i;
        const unsigned eb = (unsigned)ig * KK;
        float fsrc, dist, r0, r1, r2, r3, r4;
        if (s < v) {
            const int j = (int)(key & 0xFFu);
            unsigned ub = (key & 0xFFFFFF00u) | 0x80u;      // midpoint-restore low bits
            unsigned bits = (ub & 0x80000000u) ? (ub ^ 0x80000000u) : ~ub;
            const float d2 = __uint_as_float(bits);
            fsrc = (float)(start + j);
            dist = sqrt_approx(fmaxf(d2, 1e-12f));
            float A = ex2_approx(EA * dist * dist);
            float t = ex2_approx(ET * dist);
            r0 = A;
            float p = A * t; r1 = p * C1;
            p *= t;          r2 = p * C2;
            p *= t;          r3 = p * C3;
            p *= t;          r4 = p * C4;
        } else {
            int m = s - v;   // padding: masked indices ascending {0..start-1} ∪ {ig} ∪ {end..}
            int pidx = (m < start) ? m : ((m == start) ? ig : end + (m - start - 1));
            fsrc = (float)pidx;
            dist = padDist;
            r0 = r1 = r2 = r3 = r4 = 0.0f;
        }
        out[eb + s]           = fsrc;
        out[nK + eb + s]      = (float)ig;
        out[2u * nK + eb + s] = dist;
        float* rp = out + 3u * nK + 5u * (eb + s);
        rp[0] = r0; rp[1] = r1; rp[2] = r2; rp[3] = r3; rp[4] = r4;
    };

    auto makekey = [&](int i, int j) -> unsigned {
        unsigned key = 0xFFFFFFFFu;
        if (j < cnt && j != i) {
            float d2 = sqv[i] + sqv[j]
                - 2.0f * (px[i] * px[j] + py[i] * py[j] + pz[i] * pz[j]);
            unsigned ub = __float_as_uint(d2);
            ub ^= ((unsigned)((int)ub >> 31)) | 0x80000000u;   // monotonic float->uint
            key = (ub & 0xFFFFFF00u) | (unsigned)j;
        }
        return key;
    };

    if (cnt <= 64) {
        // ---------- fast path A: 64-key register bitonic sort, one node per warp ----------
        const int i = warp + WARPS * blockIdx.y;
        if (i >= cnt) return;

        unsigned k0 = makekey(i, lane);
        unsigned k1 = makekey(i, lane + 32);

        #pragma unroll
        for (int s = 2; s <= 16; s <<= 1) {
            #pragma unroll
            for (int d = s >> 1; d >= 1; d >>= 1) {
                bool km = ((lane & d) == 0) == ((lane & s) == 0);
                k0 = cmpex(k0, d, km);
                k1 = cmpex(k1, d, km);
            }
        }
        #pragma unroll
        for (int d = 16; d >= 1; d >>= 1) {       // stage s=32
            bool pm = ((lane & d) == 0);
            k0 = cmpex(k0, d, pm);
            k1 = cmpex(k1, d, !pm);
        }
        { unsigned a = min(k0, k1), b = max(k0, k1); k0 = a; k1 = b; }  // s=64, d=32
        #pragma unroll
        for (int d = 16; d >= 1; d >>= 1) {
            bool pm = ((lane & d) == 0);
            k0 = cmpex(k0, d, pm);
            k1 = cmpex(k1, d, pm);
        }

        emitk(i, lane, k0);
        if (lane < KK - 32) emitk(i, lane + 32, k1);
    } else if (cnt <= 128) {
        // ---------- fast path B: 128-key register bitonic sort, ONE node per warp ----------
        const int i = warp + WARPS * blockIdx.y;   // SPLIT=16 -> i in [0,128)
        if (i >= cnt) return;

        unsigned k0 = makekey(i, lane);
        unsigned k1 = makekey(i, lane + 32);
        unsigned k2 = makekey(i, lane + 64);
        unsigned k3 = makekey(i, lane + 96);

        // stages s=2..16: cross-lane, same predicate all regs
        #pragma unroll
        for (int s = 2; s <= 16; s <<= 1) {
            #pragma unroll
            for (int d = s >> 1; d >= 1; d >>= 1) {
                bool km = ((lane & d) == 0) == ((lane & s) == 0);
                k0 = cmpex(k0, d, km);
                k1 = cmpex(k1, d, km);
                k2 = cmpex(k2, d, km);
                k3 = cmpex(k3, d, km);
            }
        }
        // stage s=32: (e&32)==0 <=> r even
        #pragma unroll
        for (int d = 16; d >= 1; d >>= 1) {
            bool pm = ((lane & d) == 0);
            k0 = cmpex(k0, d, pm);
            k1 = cmpex(k1, d, !pm);
            k2 = cmpex(k2, d, pm);
            k3 = cmpex(k3, d, !pm);
        }
        // stage s=64: d=32 in-register; direction by (e&64): r<2 asc, r>=2 desc
        { unsigned a = min(k0, k1), b = max(k0, k1); k0 = a; k1 = b; }
        { unsigned a = max(k2, k3), b = min(k2, k3); k2 = a; k3 = b; }
        #pragma unroll
        for (int d = 16; d >= 1; d >>= 1) {
            bool pm = ((lane & d) == 0);
            k0 = cmpex(k0, d, pm);
            k1 = cmpex(k1, d, pm);
            k2 = cmpex(k2, d, !pm);
            k3 = cmpex(k3, d, !pm);
        }
        // stage s=128: d=64, d=32 in-register, then d=16..1 all ascending
        { unsigned a = min(k0, k2), b = max(k0, k2); k0 = a; k2 = b; }
        { unsigned a = min(k1, k3), b = max(k1, k3); k1 = a; k3 = b; }
        { unsigned a = min(k0, k1), b = max(k0, k1); k0 = a; k1 = b; }
        { unsigned a = min(k2, k3), b = max(k2, k3); k2 = a; k3 = b; }
        #pragma unroll
        for (int d = 16; d >= 1; d >>= 1) {
            bool pm = ((lane & d) == 0);
            k0 = cmpex(k0, d, pm);
            k1 = cmpex(k1, d, pm);
            k2 = cmpex(k2, d, pm);
            k3 = cmpex(k3, d, pm);
        }

        // ranks 0..31 in k0, 32..63 in k1 (k2,k3 = ranks >= 64, unused)
        emitk(i, lane, k0);
        if (lane < KK - 32) emitk(i, lane + 32, k1);
    } else {
        // ---------- fallback (cnt>128, ~never): counting rank via smem keys ----------
        unsigned* kw = keys[warp];
        for (int i = warp + WARPS * blockIdx.y; i < cnt; i += WARPS * SPLIT) {
            for (int j = lane; j < cntR; j += 32)
                kw[j] = makekey(i, j);
            __syncwarp();
            {
                const int j0 = lane, j1 = lane + 32;
                const unsigned k0 = kw[j0];
                const unsigned k1 = (j1 < cntR) ? kw[j1] : 0xFFFFFFFFu;
                int r0 = 0, r1 = 0;
                #pragma unroll 4
                for (int kb = 0; kb < cntR; kb += 4) {
                    const uint4 q = *(const uint4*)&kw[kb];
                    r0 += (q.x < k0) + (q.y < k0) + (q.z < k0) + (q.w < k0);
                    r1 += (q.x < k1) + (q.y < k1) + (q.z < k1) + (q.w < k1);
                }
                if (r0 < KK) slotK[warp][r0] = k0;
                if (r1 < KK) slotK[warp][r1] = k1;
            }
            for (int jb = 64; jb < cnt; jb += 32) {
                const int j0 = jb + lane;
                const unsigned k0 = (j0 < cntR) ? kw[j0] : 0xFFFFFFFFu;
                int r0 = 0;
                #pragma unroll 4
                for (int kb = 0; kb < cntR; kb += 4) {
                    const uint4 q = *(const uint4*)&kw[kb];
                    r0 += (q.x < k0) + (q.y < k0) + (q.z < k0) + (q.w < k0);
                }
                if (r0 < KK) slotK[warp][r0] = k0;
            }
            __syncwarp();
            for (int s = lane; s < KK; s += 32)
                emitk(i, s, (s < v) ? slotK[warp][s] : 0u);
            __syncwarp();
        }
    }
}

extern "C" void kernel_launch(void* const* d_in, const int* in_sizes, int n_in,
                              void* d_out, int out_size)
{
    const float* pos    = (const float*)d_in[0];
    const int*   batchw = (const int*)d_in[1];
    float*       out    = (float*)d_out;
    dim3 grid(NG, SPLIT);
    knn_rdf_kernel<<<grid, 256>>>(pos, batchw, out);
}

// round 12
// speedup vs baseline: 1.4600x; 1.1024x over previous
#include <cuda_runtime.h>
#include <math.h>

#define NN 16384
#define NG 256
#define KK 50
#define NB 5
#define MAXC 192     // hard cap; counting fallback handles (128, 192]
#define WARPS 8
#define SPLIT 16
#define BIGD 1e10f

__device__ int g_bounds[NG + 1];   // lower_bound(batch, g) for g in [0, NG]

__device__ __forceinline__ float ex2_approx(float x) {
    float r; asm("ex2.approx.f32 %0, %1;" : "=f"(r) : "f"(x)); return r;
}
__device__ __forceinline__ float sqrt_approx(float x) {
    float r; asm("sqrt.approx.f32 %0, %1;" : "=f"(r) : "f"(x)); return r;
}

// one bitonic compare-exchange step (cross-lane, distance d)
__device__ __forceinline__ unsigned cmpex(unsigned k, int d, bool keep_min) {
    unsigned o = __shfl_xor_sync(0xFFFFFFFFu, k, d);
    unsigned mn = min(k, o), mx = max(k, o);
    return keep_min ? mn : mx;
}

// ---- kernel 1: all graph boundaries via parallel change-scan (no chains) ----
__global__ void bounds_kernel(const int* __restrict__ batch_w) {
    const bool is64 = (batch_w[NN - 1] == 0);   // int64 layout: high word at odd index
    const int i = blockIdx.x * blockDim.x + threadIdx.x;
    if (i >= NN) return;
    auto bval = [&](int idx) -> int { return batch_w[is64 ? 2 * idx : idx]; };
    const int cur  = bval(i);
    const int prev = (i == 0) ? -1 : bval(i - 1);
    // lower_bound(batch, g) == i exactly for g in (prev, cur]
    for (int gg = prev + 1; gg <= cur; ++gg) g_bounds[gg] = i;
    if (i == NN - 1)
        for (int gg = cur + 1; gg <= NG; ++gg) g_bounds[gg] = NN;
}

// Output layout (float32, out_size = 8*N*K):
//   [0,      nK)  : edge_index row 0 (src)
//   [nK,    2nK)  : edge_index row 1 (dst)
//   [2nK,   3nK)  : dist
//   [3nK,   8nK)  : rdf [nK,5] row-major
__global__ __launch_bounds__(256, 8) void knn_rdf_kernel(
    const float* __restrict__ pos,
    float*       __restrict__ out)
{
    __shared__ float px[MAXC], py[MAXC], pz[MAXC], sqv[MAXC];
    __shared__ __align__(16) unsigned keys[WARPS][MAXC];  // fallback (cnt>128) only
    __shared__ unsigned slotK[WARPS][KK];                 // fallback only

    const int g   = blockIdx.x;
    const int tid = threadIdx.x;

    const int start = g_bounds[g];
    const int end   = g_bounds[g + 1];
    int cnt = end - start;
    if (cnt <= 0) return;
    if (cnt > MAXC) cnt = MAXC;   // safety clamp (never expected)
    // whole-block early exit: this block's warps own nodes [8*y, 8*y+8) (+ fallback strides)
    if (cnt <= 128 && WARPS * blockIdx.y >= cnt) return;
    const int cntR = (cnt + 3) & ~3;

    // stage this graph's positions + squared norms
    for (int j = tid; j < cnt; j += blockDim.x) {
        float x = pos[3 * (start + j) + 0];
        float y = pos[3 * (start + j) + 1];
        float z = pos[3 * (start + j) + 2];
        px[j] = x; py[j] = y; pz[j] = z;
        sqv[j] = x * x + y * y + z * z;
    }
    __syncthreads();

    const int warp = tid >> 5, lane = tid & 31;
    const unsigned nK = (unsigned)NN * KK;     // 819200, fits 32-bit
    const float EA = -0.11541560327111707f;    // -0.08 * log2(e)
    const float ET =  0.57707801635558534f;    //  0.40 * log2(e)
    const float C1 = 0.60653065971263342360f;
    const float C2 = 0.13533528323661270231f;
    const float C3 = 0.01110899653824230650f;
    const float C4 = 3.35462627902511838821e-4f;
    const float padDist = sqrtf(BIGD);

    const int v = min(cnt - 1, KK);            // valid (non-padding) slots per node

    // emit slot s of node i directly from a sort key (d2 decoded from key bits)
    auto emitk = [&](int i, int s, unsigned key) {
        const int ig = start + i;
        const unsigned eb = (unsigned)ig * KK;
        float fsrc, dist, r0, r1, r2, r3, r4;
        if (s < v) {
            const int j = (int)(key & 0xFFu);
            unsigned ub = (key & 0xFFFFFF00u) | 0x80u;      // midpoint-restore low bits
            unsigned bits = (ub & 0x80000000u) ? (ub ^ 0x80000000u) : ~ub;
            const float d2 = __uint_as_float(bits);
            fsrc = (float)(start + j);
            dist = sqrt_approx(fmaxf(d2, 1e-12f));
            float A = ex2_approx(EA * dist * dist);
            float t = ex2_approx(ET * dist);
            r0 = A;
            float p = A * t; r1 = p * C1;
            p *= t;          r2 = p * C2;
            p *= t;          r3 = p * C3;
            p *= t;          r4 = p * C4;
        } else {
            int m = s - v;   // padding: masked indices ascending {0..start-1} ∪ {ig} ∪ {end..}
            int pidx = (m < start) ? m : ((m == start) ? ig : end + (m - start - 1));
            fsrc = (float)pidx;
            dist = padDist;
            r0 = r1 = r2 = r3 = r4 = 0.0f;
        }
        out[eb + s]           = fsrc;
        out[nK + eb + s]      = (float)ig;
        out[2u * nK + eb + s] = dist;
        float* rp = out + 3u * nK + 5u * (eb + s);
        rp[0] = r0; rp[1] = r1; rp[2] = r2; rp[3] = r3; rp[4] = r4;
    };

    auto makekey = [&](int i, int j) -> unsigned {
        unsigned key = 0xFFFFFFFFu;
        if (j < cnt && j != i) {
            float d2 = sqv[i] + sqv[j]
                - 2.0f * (px[i] * px[j] + py[i] * py[j] + pz[i] * pz[j]);
            unsigned ub = __float_as_uint(d2);
            ub ^= ((unsigned)((int)ub >> 31)) | 0x80000000u;   // monotonic float->uint
            key = (ub & 0xFFFFFF00u) | (unsigned)j;
        }
        return key;
    };

    if (cnt <= 64) {
        // ---------- fast path A: 64-key register bitonic sort, one node per warp ----------
        const int i = warp + WARPS * blockIdx.y;
        if (i >= cnt) return;

        unsigned k0 = makekey(i, lane);
        unsigned k1 = makekey(i, lane + 32);

        #pragma unroll
        for (int s = 2; s <= 16; s <<= 1) {
            #pragma unroll
            for (int d = s >> 1; d >= 1; d >>= 1) {
                bool km = ((lane & d) == 0) == ((lane & s) == 0);
                k0 = cmpex(k0, d, km);
                k1 = cmpex(k1, d, km);
            }
        }
        #pragma unroll
        for (int d = 16; d >= 1; d >>= 1) {       // stage s=32
            bool pm = ((lane & d) == 0);
            k0 = cmpex(k0, d, pm);
            k1 = cmpex(k1, d, !pm);
        }
        { unsigned a = min(k0, k1), b = max(k0, k1); k0 = a; k1 = b; }  // s=64, d=32
        #pragma unroll
        for (int d = 16; d >= 1; d >>= 1) {
            bool pm = ((lane & d) == 0);
            k0 = cmpex(k0, d, pm);
            k1 = cmpex(k1, d, pm);
        }

        emitk(i, lane, k0);
        if (lane < KK - 32) emitk(i, lane + 32, k1);
    } else if (cnt <= 128) {
        // ---------- fast path B: 128-key register bitonic sort, ONE node per warp ----------
        const int i = warp + WARPS * blockIdx.y;   // SPLIT=16 -> i in [0,128)
        if (i >= cnt) return;

        unsigned k0 = makekey(i, lane);
        unsigned k1 = makekey(i, lane + 32);
        unsigned k2 = makekey(i, lane + 64);
        unsigned k3 = makekey(i, lane + 96);

        // stages s=2..16: cross-lane, same predicate all regs
        #pragma unroll
        for (int s = 2; s <= 16; s <<= 1) {
            #pragma unroll
            for (int d = s >> 1; d >= 1; d >>= 1) {
                bool km = ((lane & d) == 0) == ((lane & s) == 0);
                k0 = cmpex(k0, d, km);
                k1 = cmpex(k1, d, km);
                k2 = cmpex(k2, d, km);
                k3 = cmpex(k3, d, km);
            }
        }
        // stage s=32: (e&32)==0 <=> r even
        #pragma unroll
        for (int d = 16; d >= 1; d >>= 1) {
            bool pm = ((lane & d) == 0);
            k0 = cmpex(k0, d, pm);
            k1 = cmpex(k1, d, !pm);
            k2 = cmpex(k2, d, pm);
            k3 = cmpex(k3, d, !pm);
        }
        // stage s=64: d=32 in-register; direction by (e&64): r<2 asc, r>=2 desc
        { unsigned a = min(k0, k1), b = max(k0, k1); k0 = a; k1 = b; }
        { unsigned a = max(k2, k3), b = min(k2, k3); k2 = a; k3 = b; }
        #pragma unroll
        for (int d = 16; d >= 1; d >>= 1) {
            bool pm = ((lane & d) == 0);
            k0 = cmpex(k0, d, pm);
            k1 = cmpex(k1, d, pm);
            k2 = cmpex(k2, d, !pm);
            k3 = cmpex(k3, d, !pm);
        }
        // stage s=128: d=64, d=32 in-register, then d=16..1 all ascending
        { unsigned a = min(k0, k2), b = max(k0, k2); k0 = a; k2 = b; }
        { unsigned a = min(k1, k3), b = max(k1, k3); k1 = a; k3 = b; }
        { unsigned a = min(k0, k1), b = max(k0, k1); k0 = a; k1 = b; }
        { unsigned a = min(k2, k3), b = max(k2, k3); k2 = a; k3 = b; }
        #pragma unroll
        for (int d = 16; d >= 1; d >>= 1) {
            bool pm = ((lane & d) == 0);
            k0 = cmpex(k0, d, pm);
            k1 = cmpex(k1, d, pm);
            k2 = cmpex(k2, d, pm);
            k3 = cmpex(k3, d, pm);
        }

        // ranks 0..31 in k0, 32..63 in k1 (k2,k3 = ranks >= 64, unused)
        emitk(i, lane, k0);
        if (lane < KK - 32) emitk(i, lane + 32, k1);
    } else {
        // ---------- fallback (cnt>128, ~never): counting rank via smem keys ----------
        unsigned* kw = keys[warp];
        for (int i = warp + WARPS * blockIdx.y; i < cnt; i += WARPS * SPLIT) {
            for (int j = lane; j < cntR; j += 32)
                kw[j] = makekey(i, j);
            __syncwarp();
            {
                const int j0 = lane, j1 = lane + 32;
                const unsigned k0 = kw[j0];
                const unsigned k1 = (j1 < cntR) ? kw[j1] : 0xFFFFFFFFu;
                int r0 = 0, r1 = 0;
                #pragma unroll 4
                for (int kb = 0; kb < cntR; kb += 4) {
                    const uint4 q = *(const uint4*)&kw[kb];
                    r0 += (q.x < k0) + (q.y < k0) + (q.z < k0) + (q.w < k0);
                    r1 += (q.x < k1) + (q.y < k1) + (q.z < k1) + (q.w < k1);
                }
                if (r0 < KK) slotK[warp][r0] = k0;
                if (r1 < KK) slotK[warp][r1] = k1;
            }
            for (int jb = 64; jb < cnt; jb += 32) {
                const int j0 = jb + lane;
                const unsigned k0 = (j0 < cntR) ? kw[j0] : 0xFFFFFFFFu;
                int r0 = 0;
                #pragma unroll 4
                for (int kb = 0; kb < cntR; kb += 4) {
                    const uint4 q = *(const uint4*)&kw[kb];
                    r0 += (q.x < k0) + (q.y < k0) + (q.z < k0) + (q.w < k0);
                }
                if (r0 < KK) slotK[warp][r0] = k0;
            }
            __syncwarp();
            for (int s = lane; s < KK; s += 32)
                emitk(i, s, (s < v) ? slotK[warp][s] : 0u);
            __syncwarp();
        }
    }
}

extern "C" void kernel_launch(void* const* d_in, const int* in_sizes, int n_in,
                              void* d_out, int out_size)
{
    const float* pos    = (const float*)d_in[0];
    const int*   batchw = (const int*)d_in[1];
    float*       out    = (float*)d_out;
    bounds_kernel<<<(NN + 255) / 256, 256>>>(batchw);
    dim3 grid(NG, SPLIT);
    knn_rdf_kernel<<<grid, 256>>>(pos, out);
}

// round 13
// speedup vs baseline: 1.4627x; 1.0019x over previous
#include <cuda_runtime.h>
#include <math.h>

#define NN 16384
#define NG 256
#define KK 50
#define NB 5
#define MAXC 192     // hard cap; counting fallback handles (128, 192]
#define WARPS 8
#define SPLIT 16
#define BIGD 1e10f

__device__ int g_bounds[NG + 1];   // lower_bound(batch, g) for g in [0, NG]

__device__ __forceinline__ float ex2_approx(float x) {
    float r; asm("ex2.approx.f32 %0, %1;" : "=f"(r) : "f"(x)); return r;
}
__device__ __forceinline__ float sqrt_approx(float x) {
    float r; asm("sqrt.approx.f32 %0, %1;" : "=f"(r) : "f"(x)); return r;
}

// one bitonic compare-exchange step (cross-lane, distance d)
__device__ __forceinline__ unsigned cmpex(unsigned k, int d, bool keep_min) {
    unsigned o = __shfl_xor_sync(0xFFFFFFFFu, k, d);
    unsigned mn = min(k, o), mx = max(k, o);
    return keep_min ? mn : mx;
}

// ---- kernel 1: all graph boundaries via parallel change-scan (no chains) ----
__global__ void bounds_kernel(const int* __restrict__ batch_w) {
    const bool is64 = (batch_w[NN - 1] == 0);   // int64 layout: high word at odd index
    const int i = blockIdx.x * blockDim.x + threadIdx.x;
    if (i >= NN) return;
    auto bval = [&](int idx) -> int { return batch_w[is64 ? 2 * idx : idx]; };
    const int cur  = bval(i);
    const int prev = (i == 0) ? -1 : bval(i - 1);
    // lower_bound(batch, g) == i exactly for g in (prev, cur]
    for (int gg = prev + 1; gg <= cur; ++gg) g_bounds[gg] = i;
    if (i == NN - 1)
        for (int gg = cur + 1; gg <= NG; ++gg) g_bounds[gg] = NN;
}

// Output layout (float32, out_size = 8*N*K):
//   [0,      nK)  : edge_index row 0 (src)
//   [nK,    2nK)  : edge_index row 1 (dst)
//   [2nK,   3nK)  : dist
//   [3nK,   8nK)  : rdf [nK,5] row-major
__global__ __launch_bounds__(256, 8) void knn_rdf_kernel(
    const float* __restrict__ pos,
    float*       __restrict__ out)
{
    __shared__ float4 p4[MAXC];                           // {x, y, z, |p|^2}
    __shared__ __align__(16) unsigned keys[WARPS][MAXC];  // fallback (cnt>128) only
    __shared__ unsigned slotK[WARPS][KK];                 // fallback only

    const int g   = blockIdx.x;
    const int tid = threadIdx.x;

    const int start = g_bounds[g];
    const int end   = g_bounds[g + 1];
    int cnt = end - start;
    if (cnt <= 0) return;
    if (cnt > MAXC) cnt = MAXC;   // safety clamp (never expected)
    // whole-block early exit: this block's warps own nodes [8*y, 8*y+8) (+ fallback strides)
    if (cnt <= 128 && WARPS * blockIdx.y >= cnt) return;
    const int cntR = (cnt + 3) & ~3;

    // stage this graph's positions + squared norms as float4
    for (int j = tid; j < cnt; j += blockDim.x) {
        float x = pos[3 * (start + j) + 0];
        float y = pos[3 * (start + j) + 1];
        float z = pos[3 * (start + j) + 2];
        p4[j] = make_float4(x, y, z, x * x + y * y + z * z);
    }
    __syncthreads();

    const int warp = tid >> 5, lane = tid & 31;
    const unsigned nK = (unsigned)NN * KK;     // 819200, fits 32-bit
    const float EA = -0.11541560327111707f;    // -0.08 * log2(e)
    const float ET =  0.57707801635558534f;    //  0.40 * log2(e)
    const float C1 = 0.60653065971263342360f;
    const float C2 = 0.13533528323661270231f;
    const float C3 = 0.01110899653824230650f;
    const float C4 = 3.35462627902511838821e-4f;
    const float padDist = sqrtf(BIGD);

    const int v = min(cnt - 1, KK);            // valid (non-padding) slots per node

    // emit slot s of node i directly from a sort key (d2 decoded from key bits)
    auto emitk = [&](int i, int s, unsigned key) {
        const int ig = start + i;
        const unsigned eb = (unsigned)ig * KK;
        float fsrc, dist, r0, r1, r2, r3, r4;
        if (s < v) {
            const int j = (int)(key & 0xFFu);
            unsigned ub = (key & 0xFFFFFF00u) | 0x80u;      // midpoint-restore low bits
            unsigned bits = (ub & 0x80000000u) ? (ub ^ 0x80000000u) : ~ub;
            const float d2 = __uint_as_float(bits);
            fsrc = (float)(start + j);
            dist = sqrt_approx(fmaxf(d2, 1e-12f));
            float A = ex2_approx(EA * dist * dist);
            float t = ex2_approx(ET * dist);
            r0 = A;
            float p = A * t; r1 = p * C1;
            p *= t;          r2 = p * C2;
            p *= t;          r3 = p * C3;
            p *= t;          r4 = p * C4;
        } else {
            int m = s - v;   // padding: masked indices ascending {0..start-1} ∪ {ig} ∪ {end..}
            int pidx = (m < start) ? m : ((m == start) ? ig : end + (m - start - 1));
            fsrc = (float)pidx;
            dist = padDist;
            r0 = r1 = r2 = r3 = r4 = 0.0f;
        }
        out[eb + s]           = fsrc;
        out[nK + eb + s]      = (float)ig;
        out[2u * nK + eb + s] = dist;
        float* rp = out + 3u * nK + 5u * (eb + s);
        rp[0] = r0; rp[1] = r1; rp[2] = r2; rp[3] = r3; rp[4] = r4;
    };

    // key from precomputed node record pi (one LDS.128 per candidate)
    auto makekey = [&](const float4 pi, int i, int j) -> unsigned {
        unsigned key = 0xFFFFFFFFu;
        if (j < cnt && j != i) {
            const float4 pj = p4[j];
            float d2 = pi.w + pj.w - 2.0f * (pi.x * pj.x + pi.y * pj.y + pi.z * pj.z);
            unsigned ub = __float_as_uint(d2);
            ub ^= ((unsigned)((int)ub >> 31)) | 0x80000000u;   // monotonic float->uint
            key = (ub & 0xFFFFFF00u) | (unsigned)j;
        }
        return key;
    };

    if (cnt <= 64) {
        // ---------- fast path A: 64-key register bitonic sort, one node per warp ----------
        const int i = warp + WARPS * blockIdx.y;
        if (i >= cnt) return;
        const float4 pi = p4[i];

        unsigned k0 = makekey(pi, i, lane);
        unsigned k1 = makekey(pi, i, lane + 32);

        #pragma unroll
        for (int s = 2; s <= 16; s <<= 1) {
            #pragma unroll
            for (int d = s >> 1; d >= 1; d >>= 1) {
                bool km = ((lane & d) == 0) == ((lane & s) == 0);
                k0 = cmpex(k0, d, km);
                k1 = cmpex(k1, d, km);
            }
        }
        #pragma unroll
        for (int d = 16; d >= 1; d >>= 1) {       // stage s=32
            bool pm = ((lane & d) == 0);
            k0 = cmpex(k0, d, pm);
            k1 = cmpex(k1, d, !pm);
        }
        { unsigned a = min(k0, k1), b = max(k0, k1); k0 = a; k1 = b; }  // s=64, d=32
        #pragma unroll
        for (int d = 16; d >= 1; d >>= 1) {
            bool pm = ((lane & d) == 0);
            k0 = cmpex(k0, d, pm);
            k1 = cmpex(k1, d, pm);
        }

        emitk(i, lane, k0);
        if (lane < KK - 32) emitk(i, lane + 32, k1);
    } else if (cnt <= 128) {
        // ---------- fast path B: 128-key register bitonic sort, ONE node per warp ----------
        const int i = warp + WARPS * blockIdx.y;   // SPLIT=16 -> i in [0,128)
        if (i >= cnt) return;
        const float4 pi = p4[i];

        unsigned k0 = makekey(pi, i, lane);
        unsigned k1 = makekey(pi, i, lane + 32);
        unsigned k2 = makekey(pi, i, lane + 64);
        unsigned k3 = makekey(pi, i, lane + 96);

        // stages s=2..16: cross-lane, same predicate all regs
        #pragma unroll
        for (int s = 2; s <= 16; s <<= 1) {
            #pragma unroll
            for (int d = s >> 1; d >= 1; d >>= 1) {
                bool km = ((lane & d) == 0) == ((lane & s) == 0);
                k0 = cmpex(k0, d, km);
                k1 = cmpex(k1, d, km);
                k2 = cmpex(k2, d, km);
                k3 = cmpex(k3, d, km);
            }
        }
        // stage s=32: (e&32)==0 <=> r even
        #pragma unroll
        for (int d = 16; d >= 1; d >>= 1) {
            bool pm = ((lane & d) == 0);
            k0 = cmpex(k0, d, pm);
            k1 = cmpex(k1, d, !pm);
            k2 = cmpex(k2, d, pm);
            k3 = cmpex(k3, d, !pm);
        }
        // stage s=64: d=32 in-register; direction by (e&64): r<2 asc, r>=2 desc
        { unsigned a = min(k0, k1), b = max(k0, k1); k0 = a; k1 = b; }
        { unsigned a = max(k2, k3), b = min(k2, k3); k2 = a; k3 = b; }
        #pragma unroll
        for (int d = 16; d >= 1; d >>= 1) {
            bool pm = ((lane & d) == 0);
            k0 = cmpex(k0, d, pm);
            k1 = cmpex(k1, d, pm);
            k2 = cmpex(k2, d, !pm);
            k3 = cmpex(k3, d, !pm);
        }
        // stage s=128: d=64, d=32 in-register; then d=16..1 cleanup for k0,k1 ONLY
        // (k2,k3 hold ranks 64..127 after the exchanges — never emitted, cleanup is dead work)
        { unsigned a = min(k0, k2); k0 = a; }
        { unsigned a = min(k1, k3); k1 = a; }
        { unsigned a = min(k0, k1), b = max(k0, k1); k0 = a; k1 = b; }
        #pragma unroll
        for (int d = 16; d >= 1; d >>= 1) {
            bool pm = ((lane & d) == 0);
            k0 = cmpex(k0, d, pm);
            k1 = cmpex(k1, d, pm);
        }

        // ranks 0..31 in k0, 32..63 in k1
        emitk(i, lane, k0);
        if (lane < KK - 32) emitk(i, lane + 32, k1);
    } else {
        // ---------- fallback (cnt>128, ~never): counting rank via smem keys ----------
        unsigned* kw = keys[warp];
        for (int i = warp + WARPS * blockIdx.y; i < cnt; i += WARPS * SPLIT) {
            const float4 pi = p4[i];
            for (int j = lane; j < cntR; j += 32)
                kw[j] = makekey(pi, i, j);
            __syncwarp();
            {
                const int j0 = lane, j1 = lane + 32;
                const unsigned k0 = kw[j0];
                const unsigned k1 = (j1 < cntR) ? kw[j1] : 0xFFFFFFFFu;
                int r0 = 0, r1 = 0;
                #pragma unroll 4
                for (int kb = 0; kb < cntR; kb += 4) {
                    const uint4 q = *(const uint4*)&kw[kb];
                    r0 += (q.x < k0) + (q.y < k0) + (q.z < k0) + (q.w < k0);
                    r1 += (q.x < k1) + (q.y < k1) + (q.z < k1) + (q.w < k1);
                }
                if (r0 < KK) slotK[warp][r0] = k0;
                if (r1 < KK) slotK[warp][r1] = k1;
            }
            for (int jb = 64; jb < cnt; jb += 32) {
                const int j0 = jb + lane;
                const unsigned k0 = (j0 < cntR) ? kw[j0] : 0xFFFFFFFFu;
                int r0 = 0;
                #pragma unroll 4
                for (int kb = 0; kb < cntR; kb += 4) {
                    const uint4 q = *(const uint4*)&kw[kb];
                    r0 += (q.x < k0) + (q.y < k0) + (q.z < k0) + (q.w < k0);
                }
                if (r0 < KK) slotK[warp][r0] = k0;
            }
            __syncwarp();
            for (int s = lane; s < KK; s += 32)
                emitk(i, s, (s < v) ? slotK[warp][s] : 0u);
            __syncwarp();
        }
    }
}

extern "C" void kernel_launch(void* const* d_in, const int* in_sizes, int n_in,
                              void* d_out, int out_size)
{
    const float* pos    = (const float*)d_in[0];
    const int*   batchw = (const int*)d_in[1];
    float*       out    = (float*)d_out;
    bounds_kernel<<<(NN + 255) / 256, 256>>>(batchw);
    dim3 grid(NG, SPLIT);
    knn_rdf_kernel<<<grid, 256>>>(pos, out);
}